// round 13
// baseline (speedup 1.0000x reference)
#include <cuda_runtime.h>
#include <cuda_fp16.h>
#include <cstdint>

#define Bn 16
#define Cn 64
#define Hn 160
#define Wn 160
#define HP 161
#define NLOG 9
#define NPIX (Bn * HP * HP)        // 414736
#define NT32 ((NPIX + 31) / 32)    // 12961 warp tiles of 32 pixels
#define NCONV 888
#define NTHR 128
#define NWARPS (NCONV * 4)
#define HW (Hn * Wn)
#define WROW2 72                   // fp16 elems per nrow in W smem (144B, padded)
#define LU_STRIDE 65
#define STAGE_OFF 9216             // staging starts after W tile
#define SMEM_BYTES (STAGE_OFF + 4 * 2 * 4096)   // 9216 + 32768 = 41984 ; LU 16640 fits

__device__ double g_dlog[NLOG];
__device__ int    g_count = 0;

__device__ __forceinline__ void mma_f16(float* d, const uint32_t* a, uint32_t b0, uint32_t b1) {
    asm volatile(
        "mma.sync.aligned.m16n8k16.row.col.f32.f16.f16.f32 "
        "{%0,%1,%2,%3}, {%4,%5,%6,%7}, {%8,%9}, {%0,%1,%2,%3};"
        : "+f"(d[0]), "+f"(d[1]), "+f"(d[2]), "+f"(d[3])
        : "r"(a[0]), "r"(a[1]), "r"(a[2]), "r"(a[3]), "r"(b0), "r"(b1));
}
__device__ __forceinline__ uint32_t pack_f16x2(float hi, float lo) {
    uint32_t r;
    asm("cvt.rn.f16x2.f32 %0, %1, %2;" : "=r"(r) : "f"(hi), "f"(lo));
    return r;
}
__device__ __forceinline__ uint32_t smem_u32(const void* p) {
    uint32_t a;
    asm("{ .reg .u64 t; cvta.to.shared.u64 t, %1; cvt.u32.u64 %0, t; }" : "=r"(a) : "l"(p));
    return a;
}
__device__ __forceinline__ void cp4(uint32_t dst, const float* src, bool ok) {
    const int sz = ok ? 4 : 0;
    asm volatile("cp.async.ca.shared.global [%0], [%1], 4, %2;"
                 :: "r"(dst), "l"(src), "r"(sz) : "memory");
}
#define CP_COMMIT() asm volatile("cp.async.commit_group;" ::: "memory")
#define CP_WAIT1()  asm volatile("cp.async.wait_group 1;" ::: "memory")

// ---- blocks 0..8: one fp32 LU each (log in fp64); last finisher writes logdet ----
__device__ void logdet_block(int r, const float* __restrict__ wgt,
                             const float* __restrict__ ldin,
                             float* __restrict__ outld,
                             unsigned char* smem_raw)
{
    float* A = reinterpret_cast<float*>(smem_raw);
    __shared__ float  s_val[2];
    __shared__ int    s_idx[2];
    __shared__ int    s_piv;
    __shared__ double s_acc;
    __shared__ int    s_ticket;

    const int tid = threadIdx.x;
    const int n   = (r == 0) ? 64 : (r <= 4 ? 32 : 16);
    const double pixw = (r == 0) ? (double)(Hn - 1) * (double)(Wn - 1)
                                 : (r <= 4 ? (double)(Wn - 1) : 1.0);
    auto chan = [&](int m) -> int {
        if (r == 0) return m;
        if (r <= 4) {
            const int t2[4][2] = {{2, 3}, {0, 1}, {1, 3}, {0, 2}};
            return 4 * (m >> 1) + t2[r - 1][m & 1];
        }
        const int t1[4] = {3, 2, 1, 0};
        return 4 * m + t1[r - 5];
    };

    for (int idx = tid; idx < n * n; idx += NTHR) {
        int ri = idx / n, ci = idx % n;
        A[ri * LU_STRIDE + ci] = wgt[chan(ri) * Cn + chan(ci)];
    }
    if (tid == 0) s_acc = 0.0;
    __syncthreads();

    for (int k = 0; k < n; k++) {
        float v = -1.0f;
        int vi = tid;
        if (tid >= k && tid < n) v = fabsf(A[tid * LU_STRIDE + k]);
        if (tid < 64) {
#pragma unroll
            for (int off = 16; off; off >>= 1) {
                float ov = __shfl_down_sync(0xffffffffu, v, off);
                int   oi = __shfl_down_sync(0xffffffffu, vi, off);
                if (ov > v) { v = ov; vi = oi; }
            }
            if ((tid & 31) == 0) { s_val[tid >> 5] = v; s_idx[tid >> 5] = vi; }
        }
        __syncthreads();
        if (tid == 0) {
            float bv = s_val[0]; int bi = s_idx[0];
            if (n > 32 && s_val[1] > bv) { bv = s_val[1]; bi = s_idx[1]; }
            s_piv = bi;
            s_acc += log((double)bv);
        }
        __syncthreads();
        const int piv = s_piv;
        if (piv != k && tid < n) {
            float t = A[k * LU_STRIDE + tid];
            A[k * LU_STRIDE + tid]   = A[piv * LU_STRIDE + tid];
            A[piv * LU_STRIDE + tid] = t;
        }
        __syncthreads();
        if (tid > k && tid < n) {
            float m = A[tid * LU_STRIDE + k] / A[k * LU_STRIDE + k];
            for (int c = k + 1; c < n; c++)
                A[tid * LU_STRIDE + c] -= m * A[k * LU_STRIDE + c];
        }
        __syncthreads();
    }

    if (tid == 0) {
        g_dlog[r] = s_acc * pixw;
        __threadfence();
        s_ticket = atomicAdd(&g_count, 1);
    }
    __syncthreads();
    if (s_ticket == NLOG - 1) {
        __threadfence();
        if (tid < Bn) {
            volatile double* gd = g_dlog;
            double s = 0.0;
#pragma unroll
            for (int k = 0; k < NLOG; k++) s += gd[k];
            outld[tid] = ldin[tid] + (float)s;
        }
        if (tid == 0) g_count = 0;
    }
}

// ---- main: cp.async-staged gather, per-warp ping-pong pipeline, f16 2-term GEMM ----
extern "C" __global__ void __launch_bounds__(NTHR)
ic1x1_kernel(const float* __restrict__ x, const float* __restrict__ wgt,
             const float* __restrict__ ldin,
             float* __restrict__ out, float* __restrict__ outld)
{
    __shared__ __align__(16) unsigned char smem_raw[SMEM_BYTES];

    const int bx  = blockIdx.x;
    const int tid = threadIdx.x;
    if (bx < NLOG) { logdet_block(bx, wgt, ldin, outld, smem_raw); return; }

    __half* wsm = reinterpret_cast<__half*>(smem_raw);

    // ---- W -> fp16 fragment pairs: per (nrow, kt, q2): 8B = {k0,k0+1 | k0+8,k0+9} ----
    for (int g = tid; g < 64 * 16; g += NTHR) {
        const int nrow = g >> 4;
        const int kt   = (g >> 2) & 3;
        const int q2g  = g & 3;
        const int k0   = kt * 16 + 2 * q2g;
        const float* wr = wgt + nrow * 64;
        uint2 v;
        v.x = pack_f16x2(wr[k0 + 1], wr[k0]);
        v.y = pack_f16x2(wr[k0 + 9], wr[k0 + 8]);
        *reinterpret_cast<uint2*>(&wsm[nrow * WROW2 + (kt * 4 + q2g) * 4]) = v;
    }
    __syncthreads();

    const int lane = tid & 31;
    const int wid  = tid >> 5;
    const int frow = lane >> 2;
    const int q2   = lane & 3;
    const int fkq  = q2 << 1;
    const int pp   = 1 - (q2 & 1);
    const int scb  = (q2 >> 1) * 4 + pp * 2;

    const __half* wsmc = wsm;
    const int wg = (bx - NLOG) * 4 + wid;

    // per-warp staging: 2 buffers x 1024 floats (item-major: [idx*32 + lane])
    float* stage = reinterpret_cast<float*>(smem_raw + STAGE_OFF) + wid * 2048;
    const uint32_t stage_u = smem_u32(stage);

    // issue 32 cp.async gathers of one half-tile (pxoff = 0 or 16) into buffer p
    auto load_half = [&](int t, int pxoff, int p) {
        const uint32_t bufb = stage_u + (uint32_t)p * 4096 + (uint32_t)lane * 4;
#pragma unroll
        for (int u = 0; u < 2; u++) {
            const int pid = t * 32 + pxoff + u * 8 + frow;
            const bool pvv = pid < NPIX;
            const int pc = pvv ? pid : 0;
            const int bb = pc / (HP * HP);
            const int rr = pc - bb * (HP * HP);
            const int iiv = rr / HP;
            const int jjv = rr - iiv * HP;
            const int si = iiv - pp;
            const bool rok = pvv && (unsigned)si < (unsigned)Hn;
            const bool o0 = rok && (unsigned)(jjv - 1) < (unsigned)Wn;
            const bool o1 = rok && jjv < Wn;
            const float* bas = x + (size_t)bb * (Cn * HW) + (scb * Hn + si) * Wn + jjv;
            const float* p0 = o0 ? bas + (HW - 1) : x;
            const float* p1 = o1 ? bas            : x;
#pragma unroll
            for (int hh = 0; hh < 8; hh++) {
                const int o = hh * 8 * HW;
                cp4(bufb + (uint32_t)((hh * 4 + u * 2 + 0) * 128), p0 + o, o0);
                cp4(bufb + (uint32_t)((hh * 4 + u * 2 + 1) * 128), p1 + o, o1);
            }
        }
        CP_COMMIT();
    };

    // m16 x n64 x k64 GEMM reading staged floats from smem
    auto gemm = [&](int p, float (*d)[4]) {
        const float* buf = stage + p * 1024 + lane;
#pragma unroll
        for (int kt = 0; kt < 4; kt++) {
            uint32_t A_h[4], A_l[4];
#pragma unroll
            for (int e = 0; e < 4; e++) {
                const int idx = (kt * 2 + (e >> 1)) * 4 + (e & 1) * 2;
                const float v0 = buf[(idx + 0) * 32];
                const float v1 = buf[(idx + 1) * 32];
                const uint32_t ph = pack_f16x2(v1, v0);
                const float2 hf = __half22float2(*reinterpret_cast<const __half2*>(&ph));
                A_h[e] = ph;
                A_l[e] = pack_f16x2(v1 - hf.y, v0 - hf.x);
            }
#pragma unroll
            for (int nt = 0; nt < 8; nt++) {
                const int nrow = nt * 8 + frow;
                uint2 bb = *reinterpret_cast<const uint2*>(
                    wsmc + nrow * WROW2 + (kt * 4 + q2) * 4);
                mma_f16(d[nt], A_h, bb.x, bb.y);
                mma_f16(d[nt], A_l, bb.x, bb.y);
            }
        }
    };

    auto scatter_half = [&](int t, int pxoff, float (*d)[4]) {
        int  ii2[2], jj2[2];
        bool pv2[2];
        float* ob2[2];
#pragma unroll
        for (int u = 0; u < 2; u++) {
            const int pid = t * 32 + pxoff + u * 8 + frow;
            pv2[u] = pid < NPIX;
            const int pc = pv2[u] ? pid : 0;
            const int bb = pc / (HP * HP);
            const int rr = pc - bb * (HP * HP);
            ii2[u] = rr / HP;
            jj2[u] = rr - ii2[u] * HP;
            ob2[u] = out + (size_t)bb * (Cn * HW);
        }
#pragma unroll
        for (int nt = 0; nt < 8; nt++) {
#pragma unroll
            for (int r = 0; r < 4; r++) {
                const int c = nt * 8 + fkq + (r & 1);
                const int P = (c >> 1) & 1, Q = c & 1;
                const int dc = (c & ~3) | ((1 - P) << 1) | (1 - Q);
                const int u  = (r >> 1) & 1;
                const int di = ii2[u] - (1 - P);
                const int dj = jj2[u] - (1 - Q);
                if (pv2[u] && (unsigned)di < (unsigned)Hn && (unsigned)dj < (unsigned)Wn)
                    ob2[u][(dc * Hn + di) * Wn + dj] = d[nt][r];
            }
        }
    };

    // ---- pipeline: buf0/buf1 ping-pong, always one load group in flight ----
    load_half(wg, 0, 0);

    for (int t = wg; t < NT32; t += NWARPS) {
        load_half(t, 16, 1);                 // in flight over gemm(buf0)

        CP_WAIT1();                          // buf0 ready
        float d[8][4];
#pragma unroll
        for (int nt = 0; nt < 8; nt++)
#pragma unroll
            for (int r = 0; r < 4; r++) d[nt][r] = 0.0f;
        gemm(0, d);
        scatter_half(t, 0, d);

        load_half(t + NWARPS, 0, 0);         // in flight over gemm(buf1)

        CP_WAIT1();                          // buf1 ready
#pragma unroll
        for (int nt = 0; nt < 8; nt++)
#pragma unroll
            for (int r = 0; r < 4; r++) d[nt][r] = 0.0f;
        gemm(1, d);
        scatter_half(t, 16, d);
    }
}

extern "C" void kernel_launch(void* const* d_in, const int* in_sizes, int n_in,
                              void* d_out, int out_size)
{
    const float *x = nullptr, *ld = nullptr, *w = nullptr;
    for (int k = 0; k < n_in; k++) {
        if (in_sizes[k] == Cn * Cn)      w  = (const float*)d_in[k];
        else if (in_sizes[k] == Bn)      ld = (const float*)d_in[k];
        else                             x  = (const float*)d_in[k];
    }
    float* out   = (float*)d_out;
    float* outld = out + (out_size - Bn);

    ic1x1_kernel<<<NLOG + NCONV, NTHR>>>(x, w, ld, out, outld);
}

// round 14
// speedup vs baseline: 1.2631x; 1.2631x over previous
#include <cuda_runtime.h>
#include <cuda_fp16.h>
#include <cstdint>

#define Bn 16
#define Cn 64
#define Hn 160
#define Wn 160
#define HP 161
#define NLOG 9
#define NPIX (Bn * HP * HP)        // 414736
#define NT32 ((NPIX + 31) / 32)    // 12961 warp tiles of 32 pixels
#define NCONV 888
#define NTHR 128
#define NWARPS (NCONV * 4)
#define HW (Hn * Wn)
#define WROW2 72                   // fp16 elems per nrow in W smem (144B, padded)
#define LU_STRIDE 65
#define SMEM_BYTES 16640           // fp32 LU (64*65*4); W needs only 9216

__device__ double g_dlog[NLOG];
__device__ int    g_count = 0;

__device__ __forceinline__ void mma_f16(float* d, const uint32_t* a, uint32_t b0, uint32_t b1) {
    asm volatile(
        "mma.sync.aligned.m16n8k16.row.col.f32.f16.f16.f32 "
        "{%0,%1,%2,%3}, {%4,%5,%6,%7}, {%8,%9}, {%0,%1,%2,%3};"
        : "+f"(d[0]), "+f"(d[1]), "+f"(d[2]), "+f"(d[3])
        : "r"(a[0]), "r"(a[1]), "r"(a[2]), "r"(a[3]), "r"(b0), "r"(b1));
}
__device__ __forceinline__ uint32_t pack_f16x2(float hi, float lo) {
    uint32_t r;
    asm("cvt.rn.f16x2.f32 %0, %1, %2;" : "=r"(r) : "f"(hi), "f"(lo));
    return r;
}

// ---- blocks 0..8: one fp32 LU each (log in fp64); last finisher writes logdet ----
__device__ void logdet_block(int r, const float* __restrict__ wgt,
                             const float* __restrict__ ldin,
                             float* __restrict__ outld,
                             unsigned char* smem_raw)
{
    float* A = reinterpret_cast<float*>(smem_raw);
    __shared__ float  s_val[2];
    __shared__ int    s_idx[2];
    __shared__ int    s_piv;
    __shared__ double s_acc;
    __shared__ int    s_ticket;

    const int tid = threadIdx.x;
    const int n   = (r == 0) ? 64 : (r <= 4 ? 32 : 16);
    const double pixw = (r == 0) ? (double)(Hn - 1) * (double)(Wn - 1)
                                 : (r <= 4 ? (double)(Wn - 1) : 1.0);
    auto chan = [&](int m) -> int {
        if (r == 0) return m;
        if (r <= 4) {
            const int t2[4][2] = {{2, 3}, {0, 1}, {1, 3}, {0, 2}};
            return 4 * (m >> 1) + t2[r - 1][m & 1];
        }
        const int t1[4] = {3, 2, 1, 0};
        return 4 * m + t1[r - 5];
    };

    for (int idx = tid; idx < n * n; idx += NTHR) {
        int ri = idx / n, ci = idx % n;
        A[ri * LU_STRIDE + ci] = wgt[chan(ri) * Cn + chan(ci)];
    }
    if (tid == 0) s_acc = 0.0;
    __syncthreads();

    for (int k = 0; k < n; k++) {
        float v = -1.0f;
        int vi = tid;
        if (tid >= k && tid < n) v = fabsf(A[tid * LU_STRIDE + k]);
        if (tid < 64) {
#pragma unroll
            for (int off = 16; off; off >>= 1) {
                float ov = __shfl_down_sync(0xffffffffu, v, off);
                int   oi = __shfl_down_sync(0xffffffffu, vi, off);
                if (ov > v) { v = ov; vi = oi; }
            }
            if ((tid & 31) == 0) { s_val[tid >> 5] = v; s_idx[tid >> 5] = vi; }
        }
        __syncthreads();
        if (tid == 0) {
            float bv = s_val[0]; int bi = s_idx[0];
            if (n > 32 && s_val[1] > bv) { bv = s_val[1]; bi = s_idx[1]; }
            s_piv = bi;
            s_acc += log((double)bv);
        }
        __syncthreads();
        const int piv = s_piv;
        if (piv != k && tid < n) {
            float t = A[k * LU_STRIDE + tid];
            A[k * LU_STRIDE + tid]   = A[piv * LU_STRIDE + tid];
            A[piv * LU_STRIDE + tid] = t;
        }
        __syncthreads();
        if (tid > k && tid < n) {
            float m = A[tid * LU_STRIDE + k] / A[k * LU_STRIDE + k];
            for (int c = k + 1; c < n; c++)
                A[tid * LU_STRIDE + c] -= m * A[k * LU_STRIDE + c];
        }
        __syncthreads();
    }

    if (tid == 0) {
        g_dlog[r] = s_acc * pixw;
        __threadfence();
        s_ticket = atomicAdd(&g_count, 1);
    }
    __syncthreads();
    if (s_ticket == NLOG - 1) {
        __threadfence();
        if (tid < Bn) {
            volatile double* gd = g_dlog;
            double s = 0.0;
#pragma unroll
            for (int k = 0; k < NLOG; k++) s += gd[k];
            outld[tid] = ldin[tid] + (float)s;
        }
        if (tid == 0) g_count = 0;
    }
}

// ---- main: 32-px warp tiles, f16 2-term GEMM, in-place prefetch (2 buffers) ----
extern "C" __global__ void __launch_bounds__(NTHR)
ic1x1_kernel(const float* __restrict__ x, const float* __restrict__ wgt,
             const float* __restrict__ ldin,
             float* __restrict__ out, float* __restrict__ outld)
{
    extern __shared__ __align__(16) unsigned char smem_raw[];

    const int bx  = blockIdx.x;
    const int tid = threadIdx.x;
    if (bx < NLOG) { logdet_block(bx, wgt, ldin, outld, smem_raw); return; }

    __half* wsm = reinterpret_cast<__half*>(smem_raw);

    // ---- W -> fp16 fragment pairs: per (nrow, kt, q2): 8B = {k0,k0+1 | k0+8,k0+9} ----
    for (int g = tid; g < 64 * 16; g += NTHR) {
        const int nrow = g >> 4;
        const int kt   = (g >> 2) & 3;
        const int q2g  = g & 3;
        const int k0   = kt * 16 + 2 * q2g;
        const float* wr = wgt + nrow * 64;
        uint2 v;
        v.x = pack_f16x2(wr[k0 + 1], wr[k0]);
        v.y = pack_f16x2(wr[k0 + 9], wr[k0 + 8]);
        *reinterpret_cast<uint2*>(&wsm[nrow * WROW2 + (kt * 4 + q2g) * 4]) = v;
    }
    __syncthreads();

    const int lane = tid & 31;
    const int frow = lane >> 2;
    const int q2   = lane & 3;
    const int fkq  = q2 << 1;
    const int pp   = 1 - (q2 & 1);
    const int scb  = (q2 >> 1) * 4 + pp * 2;

    const __half* wsmc = wsm;
    const int wg = (bx - NLOG) * 4 + (tid >> 5);

    struct Meta { int ii[2]; int jj[2]; float* ob[2]; };

    // issue the 32 gathers of one half-tile into buf; record scatter meta
    auto load_half = [&](int t, int pxoff, float* buf, Meta& m) {
#pragma unroll
        for (int u = 0; u < 2; u++) {
            const int pid = t * 32 + pxoff + u * 8 + frow;
            const bool pvv = pid < NPIX;
            const int pc = pvv ? pid : 0;
            const int bb = pc / (HP * HP);
            const int rr = pc - bb * (HP * HP);
            const int iiv = rr / HP;
            const int jjv = rr - iiv * HP;
            m.ii[u] = pvv ? iiv : -1000;      // poison => all scatter predicates fail
            m.jj[u] = jjv;
            m.ob[u] = out + (size_t)bb * (Cn * HW);
            const int si = iiv - pp;
            const bool rok = pvv && (unsigned)si < (unsigned)Hn;
            const bool o0 = rok && (unsigned)(jjv - 1) < (unsigned)Wn;
            const bool o1 = rok && jjv < Wn;
            const float* bas = x + (size_t)bb * (Cn * HW) + (scb * Hn + si) * Wn + jjv;
#pragma unroll
            for (int hh = 0; hh < 8; hh++) {
                const int o = hh * 8 * HW;
                buf[hh * 4 + u * 2 + 0] = o0 ? bas[o + (HW - 1)] : 0.0f;
                buf[hh * 4 + u * 2 + 1] = o1 ? bas[o]            : 0.0f;
            }
        }
    };

    // m16 x n64 x k64 GEMM, z split exactly into two fp16s, W in fp16
    auto gemm = [&](const float* buf, float (*d)[4]) {
#pragma unroll
        for (int kt = 0; kt < 4; kt++) {
            uint32_t A_h[4], A_l[4];
#pragma unroll
            for (int e = 0; e < 4; e++) {
                const int idx = (kt * 2 + (e >> 1)) * 4 + (e & 1) * 2;
                const float v0 = buf[idx + 0];
                const float v1 = buf[idx + 1];
                const uint32_t ph = pack_f16x2(v1, v0);
                const float2 hf = __half22float2(*reinterpret_cast<const __half2*>(&ph));
                A_h[e] = ph;
                A_l[e] = pack_f16x2(v1 - hf.y, v0 - hf.x);
            }
#pragma unroll
            for (int nt = 0; nt < 8; nt++) {
                const int nrow = nt * 8 + frow;
                uint2 bb = *reinterpret_cast<const uint2*>(
                    wsmc + nrow * WROW2 + (kt * 4 + q2) * 4);
                mma_f16(d[nt], A_h, bb.x, bb.y);
                mma_f16(d[nt], A_l, bb.x, bb.y);
            }
        }
    };

    auto scatter_half = [&](const Meta& m, float (*d)[4]) {
#pragma unroll
        for (int nt = 0; nt < 8; nt++) {
#pragma unroll
            for (int r = 0; r < 4; r++) {
                const int c = nt * 8 + fkq + (r & 1);
                const int P = (c >> 1) & 1, Q = c & 1;
                const int dc = (c & ~3) | ((1 - P) << 1) | (1 - Q);
                const int u  = (r >> 1) & 1;
                const int di = m.ii[u] - (1 - P);
                const int dj = m.jj[u] - (1 - Q);
                if ((unsigned)di < (unsigned)Hn && (unsigned)dj < (unsigned)Wn)
                    m.ob[u][(dc * Hn + di) * Wn + dj] = d[nt][r];
            }
        }
    };

    // ---- pipeline: 2 data buffers (A reloaded in place), 3 small meta sets ----
    float rvA[32], rvC[32];
    Meta  mA, mC, mN;
    load_half(wg, 0, rvA, mA);

    for (int t = wg; t < NT32; t += NWARPS) {
        load_half(t, 16, rvC, mC);            // in flight over gemm(rvA)

        float d[8][4];
#pragma unroll
        for (int nt = 0; nt < 8; nt++)
#pragma unroll
            for (int r = 0; r < 4; r++) d[nt][r] = 0.0f;
        gemm(rvA, d);

        load_half(t + NWARPS, 0, rvA, mN);    // rvA dead -> reload in place

        scatter_half(mA, d);

#pragma unroll
        for (int nt = 0; nt < 8; nt++)
#pragma unroll
            for (int r = 0; r < 4; r++) d[nt][r] = 0.0f;
        gemm(rvC, d);
        scatter_half(mC, d);

        mA = mN;                              // 8-reg meta rotate
    }
}

extern "C" void kernel_launch(void* const* d_in, const int* in_sizes, int n_in,
                              void* d_out, int out_size)
{
    const float *x = nullptr, *ld = nullptr, *w = nullptr;
    for (int k = 0; k < n_in; k++) {
        if (in_sizes[k] == Cn * Cn)      w  = (const float*)d_in[k];
        else if (in_sizes[k] == Bn)      ld = (const float*)d_in[k];
        else                             x  = (const float*)d_in[k];
    }
    float* out   = (float*)d_out;
    float* outld = out + (out_size - Bn);

    ic1x1_kernel<<<NLOG + NCONV, NTHR, SMEM_BYTES>>>(x, w, ld, out, outld);
}